// round 11
// baseline (speedup 1.0000x reference)
#include <cuda_runtime.h>
#include <cuda_bf16.h>
#include <math.h>

// Problem constants
#define Bc 4
#define Tc 2048
#define Dc 1024
#define Hc 8
#define DKc 128        // D/H
#define DVc 256        // 2D/H
#define CC 64          // chunk size
#define NCHUNK 32      // T / C
#define MROWS (Bc*Tc)  // 8192

// ---------------- scratch (device globals; no runtime alloc allowed) -------
__device__ float g_q[MROWS * Hc * DKc];   // 8192 x 1024
__device__ float g_k[MROWS * Hc * DKc];   // 8192 x 1024
__device__ float g_v[MROWS * Hc * DVc];   // 8192 x 2048
__device__ float g_g[MROWS * Hc * DVc];   // 8192 x 2048
__device__ float g_o[MROWS * Hc * DVc];   // 8192 x 2048

// ---------------- SGEMM: C[M,N] = A[M,K] @ B[K,N], row-major, fp32 ---------
// 128x128 block tile, BK=8, 256 threads, 8x8 micro-tile, double-buffered SMEM.
// Requires M%128==0, N%128==0, K%16==0 (true for all calls here).
__global__ void __launch_bounds__(256) sgemm128(const float* __restrict__ A,
                                                const float* __restrict__ B,
                                                float* __restrict__ C,
                                                int M, int N, int K)
{
    __shared__ float As[2][8][128];
    __shared__ float Bs[2][8][128];

    const int tid  = threadIdx.x;
    const int brow = blockIdx.y * 128;
    const int bcol = blockIdx.x * 128;

    const int aRow = tid >> 1;          // 0..127
    const int aCol = (tid & 1) << 2;    // 0 or 4
    const int bRow = tid >> 5;          // 0..7
    const int bCol = (tid & 31) << 2;   // 0..124

    const int tx = (tid & 15) << 3;     // out col base in tile
    const int ty = (tid >> 4) << 3;     // out row base in tile

    float acc[8][8];
#pragma unroll
    for (int i = 0; i < 8; i++)
#pragma unroll
        for (int j = 0; j < 8; j++) acc[i][j] = 0.f;

    const float* Aptr = A + (size_t)(brow + aRow) * K + aCol;
    const float* Bptr = B + (size_t)bRow * N + bcol + bCol;

    // preload slab 0
    float4 av = *(const float4*)(Aptr);
    float4 bv = *(const float4*)(Bptr);
    As[0][aCol + 0][aRow] = av.x;
    As[0][aCol + 1][aRow] = av.y;
    As[0][aCol + 2][aRow] = av.z;
    As[0][aCol + 3][aRow] = av.w;
    *(float4*)&Bs[0][bRow][bCol] = bv;
    __syncthreads();

    int buf = 0;
    for (int k0 = 0; k0 < K; k0 += 8) {
        // prefetch next slab into registers while computing this one
        const bool has_next = (k0 + 8) < K;
        if (has_next) {
            av = *(const float4*)(Aptr + (k0 + 8));
            bv = *(const float4*)(Bptr + (size_t)(k0 + 8) * N);
        }

#pragma unroll
        for (int kk = 0; kk < 8; kk++) {
            float ar[8], br[8];
            *(float4*)(ar)     = *(float4*)&As[buf][kk][ty];
            *(float4*)(ar + 4) = *(float4*)&As[buf][kk][ty + 4];
            *(float4*)(br)     = *(float4*)&Bs[buf][kk][tx];
            *(float4*)(br + 4) = *(float4*)&Bs[buf][kk][tx + 4];
#pragma unroll
            for (int i = 0; i < 8; i++)
#pragma unroll
                for (int j = 0; j < 8; j++)
                    acc[i][j] = fmaf(ar[i], br[j], acc[i][j]);
        }

        if (has_next) {
            const int nb = buf ^ 1;
            As[nb][aCol + 0][aRow] = av.x;
            As[nb][aCol + 1][aRow] = av.y;
            As[nb][aCol + 2][aRow] = av.z;
            As[nb][aCol + 3][aRow] = av.w;
            *(float4*)&Bs[nb][bRow][bCol] = bv;
            __syncthreads();
            buf = nb;
        }
    }

#pragma unroll
    for (int i = 0; i < 8; i++) {
        float4* crow = (float4*)(C + (size_t)(brow + ty + i) * N + bcol + tx);
        crow[0] = make_float4(acc[i][0], acc[i][1], acc[i][2], acc[i][3]);
        crow[1] = make_float4(acc[i][4], acc[i][5], acc[i][6], acc[i][7]);
    }
}

// ---------------- RoPE (in place on q and k), q also scaled by DK^-0.5 -----
__global__ void __launch_bounds__(256) rope_kernel(float* __restrict__ q,
                                                   float* __restrict__ k)
{
    size_t idx = (size_t)blockIdx.x * blockDim.x + threadIdx.x;
    const size_t total = (size_t)Bc * Tc * Hc * 64;   // pairs
    if (idx >= total) return;
    int j = (int)(idx & 63);
    size_t rest = idx >> 6;
    int h = (int)(rest & 7);
    size_t bt = rest >> 3;              // b*T + t
    int t = (int)(bt & (Tc - 1));

    float invf = exp2f(-(float)j / 64.f * 13.28771237954945f); // log2(10000)
    float f = (float)t * invf;
    float sv, cv;
    sincosf(f, &sv, &cv);

    size_t base = bt * (Hc * DKc) + (size_t)h * DKc + j;
    const float sc = 0.08838834764831843f; // 128^-0.5

    float q1 = q[base], q2 = q[base + 64];
    q[base]      = (q1 * cv - q2 * sv) * sc;
    q[base + 64] = (q2 * cv + q1 * sv) * sc;

    float k1 = k[base], k2 = k[base + 64];
    k[base]      = k1 * cv - k2 * sv;
    k[base + 64] = k2 * cv + k1 * sv;
}

// ---------------- chunked retention -----------------------------------------
// One block per (b, h, dv-slice of 64). Sequential over 32 chunks.
// SMEM (pad=68 floats/row): qT[128][68], kT[128][68], S[128][68],
//                           vs[64][68], attn[64][68], gpow[65]
#define PADR 68
#define SM_QT   0
#define SM_KT   (SM_QT + 128 * PADR)
#define SM_S    (SM_KT + 128 * PADR)
#define SM_VS   (SM_S  + 128 * PADR)
#define SM_ATT  (SM_VS + 64 * PADR)
#define SM_GPOW (SM_ATT + 64 * PADR)
#define SM_FLOATS (SM_GPOW + 65)

__global__ void __launch_bounds__(256) retention_kernel(
    const float* __restrict__ q, const float* __restrict__ k,
    const float* __restrict__ v, float* __restrict__ o)
{
    extern __shared__ float sm[];
    float* qT   = sm + SM_QT;
    float* kT   = sm + SM_KT;
    float* S    = sm + SM_S;
    float* vs   = sm + SM_VS;
    float* attn = sm + SM_ATT;
    float* gpow = sm + SM_GPOW;

    const int bid = blockIdx.x;           // b*32 + h*4 + s
    const int b = bid >> 5;
    const int h = (bid >> 2) & 7;
    const int s = bid & 3;
    const int e0 = s * 64;
    const int tid = threadIdx.x;

    const float gamma = 1.f - exp2f(-5.f - (float)h);
    if (tid < 65) gpow[tid] = powf(gamma, (float)tid);
    for (int idx = tid; idx < 128 * PADR; idx += 256) S[idx] = 0.f;
    __syncthreads();

    const int ti = tid >> 4;   // 0..15
    const int tj = tid & 15;   // 0..15

    for (int n = 0; n < NCHUNK; n++) {
        const size_t rowbase = (size_t)(b * Tc + n * CC);
        // load q,k transposed [d][i]; v slice [i][e]
        for (int idx = tid; idx < 64 * 128; idx += 256) {
            int i = idx >> 7, d = idx & 127;
            size_t gq = (rowbase + i) * (Hc * DKc) + h * DKc + d;
            qT[d * PADR + i] = q[gq];
            kT[d * PADR + i] = k[gq];
        }
        for (int idx = tid; idx < 64 * 64; idx += 256) {
            int i = idx >> 6, e = idx & 63;
            vs[i * PADR + e] = v[(rowbase + i) * (Hc * DVc) + h * DVc + e0 + e];
        }
        __syncthreads();

        // ---- attn = (q k^T) * M ---- 4x4 tile per thread
        {
            float a4[4][4] = {};
#pragma unroll 4
            for (int d = 0; d < 128; d++) {
                float ar[4], br[4];
                *(float4*)ar = *(float4*)&qT[d * PADR + 4 * ti];
                *(float4*)br = *(float4*)&kT[d * PADR + 4 * tj];
#pragma unroll
                for (int r = 0; r < 4; r++)
#pragma unroll
                    for (int c = 0; c < 4; c++)
                        a4[r][c] = fmaf(ar[r], br[c], a4[r][c]);
            }
#pragma unroll
            for (int r = 0; r < 4; r++) {
                int i = 4 * ti + r;
#pragma unroll
                for (int c = 0; c < 4; c++) {
                    int j = 4 * tj + c;
                    attn[i * PADR + j] = (i >= j) ? a4[r][c] * gpow[i - j] : 0.f;
                }
            }
        }
        __syncthreads();

        // ---- o = attn @ v  +  dec_q * (q @ S_old) ----
        {
            float a4[4][4] = {};
#pragma unroll 4
            for (int d = 0; d < 128; d++) {
                float ar[4], br[4];
                *(float4*)ar = *(float4*)&qT[d * PADR + 4 * ti];
                *(float4*)br = *(float4*)&S[d * PADR + 4 * tj];
#pragma unroll
                for (int r = 0; r < 4; r++)
#pragma unroll
                    for (int c = 0; c < 4; c++)
                        a4[r][c] = fmaf(ar[r], br[c], a4[r][c]);
            }
#pragma unroll
            for (int r = 0; r < 4; r++) {
                float dq = gpow[4 * ti + r + 1];
#pragma unroll
                for (int c = 0; c < 4; c++) a4[r][c] *= dq;
            }
#pragma unroll 4
            for (int j = 0; j < 64; j++) {
                float br[4];
                *(float4*)br = *(float4*)&vs[j * PADR + 4 * tj];
#pragma unroll
                for (int r = 0; r < 4; r++) {
                    float av = attn[(4 * ti + r) * PADR + j];
#pragma unroll
                    for (int c = 0; c < 4; c++)
                        a4[r][c] = fmaf(av, br[c], a4[r][c]);
                }
            }
#pragma unroll
            for (int r = 0; r < 4; r++) {
                size_t orow = (rowbase + 4 * ti + r) * (Hc * DVc) + h * DVc + e0 + 4 * tj;
                *(float4*)&o[orow] = make_float4(a4[r][0], a4[r][1], a4[r][2], a4[r][3]);
            }
        }
        __syncthreads();   // everyone done reading old S

        // ---- S = gamma^C * S + (k * dec_k)^T @ v ----  8x4 tile per thread
        {
            const int d0 = ti * 8;    // 0..120
            const int eg = tj * 4;    // 0..60
            float acc2[8][4] = {};
#pragma unroll 4
            for (int j = 0; j < 64; j++) {
                float dk = gpow[63 - j];
                float vv[4];
                *(float4*)vv = *(float4*)&vs[j * PADR + eg];
#pragma unroll
                for (int r = 0; r < 8; r++) {
                    float kd = kT[(d0 + r) * PADR + j] * dk;
#pragma unroll
                    for (int c = 0; c < 4; c++)
                        acc2[r][c] = fmaf(kd, vv[c], acc2[r][c]);
                }
            }
            const float gC = gpow[64];
#pragma unroll
            for (int r = 0; r < 8; r++)
#pragma unroll
                for (int c = 0; c < 4; c++) {
                    float* sp = &S[(d0 + r) * PADR + eg + c];
                    *sp = gC * (*sp) + acc2[r][c];
                }
        }
        __syncthreads();
    }
}

// ---------------- RMSNorm over DV + SiLU gate (in place on o) ---------------
__global__ void __launch_bounds__(256) norm_gate_kernel(
    float* __restrict__ o, const float* __restrict__ g,
    const float* __restrict__ norm_w)
{
    const int warp = threadIdx.x >> 5, lane = threadIdx.x & 31;
    const size_t row = (size_t)blockIdx.x * 8 + warp;   // B*T*H rows
    float* orow = o + row * DVc;
    const float* grow = g + row * DVc;

    float vals[8];
    float ss = 0.f;
#pragma unroll
    for (int c = 0; c < 8; c++) {
        float x = orow[lane + 32 * c];
        vals[c] = x;
        ss += x * x;
    }
#pragma unroll
    for (int off = 16; off; off >>= 1) ss += __shfl_xor_sync(0xffffffffu, ss, off);
    const float rinv = rsqrtf(ss * (1.f / DVc) + 1e-5f);

#pragma unroll
    for (int c = 0; c < 8; c++) {
        int e = lane + 32 * c;
        float gv = grow[e];
        float gate = gv / (1.f + expf(-gv));         // g * sigmoid(g)
        orow[e] = vals[c] * rinv * norm_w[e] * gate;
    }
}

// ---------------- launch -----------------------------------------------------
extern "C" void kernel_launch(void* const* d_in, const int* in_sizes, int n_in,
                              void* d_out, int out_size)
{
    const float* x      = (const float*)d_in[0];
    const float* Wq     = (const float*)d_in[1];
    const float* Wk     = (const float*)d_in[2];
    const float* Wv     = (const float*)d_in[3];
    const float* Wg     = (const float*)d_in[4];
    const float* Wo     = (const float*)d_in[5];
    const float* norm_w = (const float*)d_in[6];
    float* out = (float*)d_out;

    float *pq, *pk, *pv, *pg, *po;
    cudaGetSymbolAddress((void**)&pq, g_q);
    cudaGetSymbolAddress((void**)&pk, g_k);
    cudaGetSymbolAddress((void**)&pv, g_v);
    cudaGetSymbolAddress((void**)&pg, g_g);
    cudaGetSymbolAddress((void**)&po, g_o);

    dim3 blk(256);
    // projections
    sgemm128<<<dim3(Hc * DKc / 128, MROWS / 128), blk>>>(x, Wq, pq, MROWS, Hc * DKc, Dc);
    sgemm128<<<dim3(Hc * DKc / 128, MROWS / 128), blk>>>(x, Wk, pk, MROWS, Hc * DKc, Dc);
    sgemm128<<<dim3(Hc * DVc / 128, MROWS / 128), blk>>>(x, Wv, pv, MROWS, Hc * DVc, Dc);
    sgemm128<<<dim3(Hc * DVc / 128, MROWS / 128), blk>>>(x, Wg, pg, MROWS, Hc * DVc, Dc);

    // rope (+ q scale)
    {
        size_t total = (size_t)Bc * Tc * Hc * 64;
        rope_kernel<<<(unsigned)((total + 255) / 256), blk>>>(pq, pk);
    }

    // retention
    {
        const int smem = SM_FLOATS * sizeof(float);
        cudaFuncSetAttribute(retention_kernel,
                             cudaFuncAttributeMaxDynamicSharedMemorySize, smem);
        retention_kernel<<<Bc * Hc * 4, blk, smem>>>(pq, pk, pv, po);
    }

    // rmsnorm + gate
    norm_gate_kernel<<<(Bc * Tc * Hc) / 8, blk>>>(po, pg, norm_w);

    // output projection
    sgemm128<<<dim3(Dc / 128, MROWS / 128), blk>>>(po, Wo, out, MROWS, Dc, Hc * DVc);
}

// round 13
// speedup vs baseline: 1.7650x; 1.7650x over previous
#include <cuda_runtime.h>
#include <cuda_bf16.h>
#include <math.h>
#include <stdint.h>

// Problem constants
#define Bc 4
#define Tc 2048
#define Dc 1024
#define Hc 8
#define DKc 128        // D/H
#define DVc 256        // 2D/H
#define CC 64          // chunk size
#define NCHUNK 32      // T / C
#define MROWS (Bc*Tc)  // 8192

// ---------------- scratch (device globals; no runtime alloc allowed) -------
__device__ float g_q[MROWS * Hc * DKc];   // 8192 x 1024
__device__ float g_k[MROWS * Hc * DKc];   // 8192 x 1024
__device__ float g_v[MROWS * Hc * DVc];   // 8192 x 2048
__device__ float g_g[MROWS * Hc * DVc];   // 8192 x 2048
__device__ float g_o[MROWS * Hc * DVc];   // 8192 x 2048

// ---------------- TF32 GEMM: C[M,N] = A[M,K] @ B[K,N], row-major -----------
// 128x128 block tile, BK=16, 256 threads (8 warps, 2x4), warp tile 64x32,
// mma.sync.m16n8k8.tf32, double-buffered SMEM, cvt.rna at SMEM store.
#define BKt 16
#define APAD 4

__device__ __forceinline__ uint32_t f2tf(float x) {
    uint32_t u;
    asm("cvt.rna.tf32.f32 %0, %1;" : "=r"(u) : "f"(x));
    return u;
}

__device__ __forceinline__ void mma_tf32(float* c,
    uint32_t a0, uint32_t a1, uint32_t a2, uint32_t a3,
    uint32_t b0, uint32_t b1)
{
    asm volatile(
        "mma.sync.aligned.m16n8k8.row.col.f32.tf32.tf32.f32 "
        "{%0,%1,%2,%3}, {%4,%5,%6,%7}, {%8,%9}, {%0,%1,%2,%3};"
        : "+f"(c[0]), "+f"(c[1]), "+f"(c[2]), "+f"(c[3])
        : "r"(a0), "r"(a1), "r"(a2), "r"(a3), "r"(b0), "r"(b1));
}

__global__ void __launch_bounds__(256) tf32gemm(const float* __restrict__ A,
                                                const float* __restrict__ B,
                                                float* __restrict__ C,
                                                int M, int N, int K)
{
    __shared__ uint32_t As[2][BKt][128 + APAD];
    __shared__ uint32_t Bs[2][BKt][128 + APAD];

    const int tid  = threadIdx.x;
    const int warp = tid >> 5;
    const int lane = tid & 31;
    const int g    = lane >> 2;    // 0..7
    const int tg   = lane & 3;     // 0..3

    const int brow = blockIdx.y * 128;
    const int bcol = blockIdx.x * 128;

    const int wm = (warp >> 2) * 64;   // 0 or 64
    const int wn = (warp & 3) * 32;    // 0,32,64,96

    float acc[4][4][4];
#pragma unroll
    for (int mt = 0; mt < 4; mt++)
#pragma unroll
        for (int nt = 0; nt < 4; nt++)
#pragma unroll
            for (int i = 0; i < 4; i++) acc[mt][nt][i] = 0.f;

    // global load mapping
    const int arow = tid >> 1;           // 0..127
    const int acb  = (tid & 1) << 3;     // 0 or 8 (col base within slab)
    const int br0  = tid >> 5;           // 0..7
    const int bcc  = (tid & 31) << 2;    // 0..124

    const float* Aptr = A + (size_t)(brow + arow) * K + acb;
    const float* Bp0  = B + (size_t)br0 * N + bcol + bcc;
    const float* Bp1  = B + (size_t)(br0 + 8) * N + bcol + bcc;

    // ---- preload slab 0 ----
    {
        float4 av0 = *(const float4*)(Aptr);
        float4 av1 = *(const float4*)(Aptr + 4);
        float4 bv0 = *(const float4*)(Bp0);
        float4 bv1 = *(const float4*)(Bp1);
        As[0][acb + 0][arow] = f2tf(av0.x);
        As[0][acb + 1][arow] = f2tf(av0.y);
        As[0][acb + 2][arow] = f2tf(av0.z);
        As[0][acb + 3][arow] = f2tf(av0.w);
        As[0][acb + 4][arow] = f2tf(av1.x);
        As[0][acb + 5][arow] = f2tf(av1.y);
        As[0][acb + 6][arow] = f2tf(av1.z);
        As[0][acb + 7][arow] = f2tf(av1.w);
        Bs[0][br0][bcc + 0] = f2tf(bv0.x);
        Bs[0][br0][bcc + 1] = f2tf(bv0.y);
        Bs[0][br0][bcc + 2] = f2tf(bv0.z);
        Bs[0][br0][bcc + 3] = f2tf(bv0.w);
        Bs[0][br0 + 8][bcc + 0] = f2tf(bv1.x);
        Bs[0][br0 + 8][bcc + 1] = f2tf(bv1.y);
        Bs[0][br0 + 8][bcc + 2] = f2tf(bv1.z);
        Bs[0][br0 + 8][bcc + 3] = f2tf(bv1.w);
    }
    __syncthreads();

    int buf = 0;
    for (int k0 = 0; k0 < K; k0 += BKt) {
        const bool has_next = (k0 + BKt) < K;
        float4 av0, av1, bv0, bv1;
        if (has_next) {
            av0 = *(const float4*)(Aptr + (k0 + BKt));
            av1 = *(const float4*)(Aptr + (k0 + BKt) + 4);
            bv0 = *(const float4*)(Bp0 + (size_t)(k0 + BKt) * N);
            bv1 = *(const float4*)(Bp1 + (size_t)(k0 + BKt) * N);
        }

        // ---- compute 2 k8 steps from current buffer ----
#pragma unroll
        for (int ks = 0; ks < BKt; ks += 8) {
            uint32_t af[4][4], bf[4][2];
#pragma unroll
            for (int mt = 0; mt < 4; mt++) {
                const int m0 = wm + mt * 16 + g;
                af[mt][0] = As[buf][ks + tg][m0];
                af[mt][1] = As[buf][ks + tg][m0 + 8];
                af[mt][2] = As[buf][ks + tg + 4][m0];
                af[mt][3] = As[buf][ks + tg + 4][m0 + 8];
            }
#pragma unroll
            for (int nt = 0; nt < 4; nt++) {
                const int n0 = wn + nt * 8 + g;
                bf[nt][0] = Bs[buf][ks + tg][n0];
                bf[nt][1] = Bs[buf][ks + tg + 4][n0];
            }
#pragma unroll
            for (int mt = 0; mt < 4; mt++)
#pragma unroll
                for (int nt = 0; nt < 4; nt++)
                    mma_tf32(acc[mt][nt], af[mt][0], af[mt][1], af[mt][2], af[mt][3],
                             bf[nt][0], bf[nt][1]);
        }

        if (has_next) {
            const int nb = buf ^ 1;
            As[nb][acb + 0][arow] = f2tf(av0.x);
            As[nb][acb + 1][arow] = f2tf(av0.y);
            As[nb][acb + 2][arow] = f2tf(av0.z);
            As[nb][acb + 3][arow] = f2tf(av0.w);
            As[nb][acb + 4][arow] = f2tf(av1.x);
            As[nb][acb + 5][arow] = f2tf(av1.y);
            As[nb][acb + 6][arow] = f2tf(av1.z);
            As[nb][acb + 7][arow] = f2tf(av1.w);
            Bs[nb][br0][bcc + 0] = f2tf(bv0.x);
            Bs[nb][br0][bcc + 1] = f2tf(bv0.y);
            Bs[nb][br0][bcc + 2] = f2tf(bv0.z);
            Bs[nb][br0][bcc + 3] = f2tf(bv0.w);
            Bs[nb][br0 + 8][bcc + 0] = f2tf(bv1.x);
            Bs[nb][br0 + 8][bcc + 1] = f2tf(bv1.y);
            Bs[nb][br0 + 8][bcc + 2] = f2tf(bv1.z);
            Bs[nb][br0 + 8][bcc + 3] = f2tf(bv1.w);
            __syncthreads();
            buf = nb;
        }
    }

    // ---- epilogue ----
#pragma unroll
    for (int mt = 0; mt < 4; mt++) {
        const int r0 = brow + wm + mt * 16 + g;
#pragma unroll
        for (int nt = 0; nt < 4; nt++) {
            const int c0 = bcol + wn + nt * 8 + 2 * tg;
            *(float2*)(C + (size_t)r0 * N + c0) =
                make_float2(acc[mt][nt][0], acc[mt][nt][1]);
            *(float2*)(C + (size_t)(r0 + 8) * N + c0) =
                make_float2(acc[mt][nt][2], acc[mt][nt][3]);
        }
    }
}

// ---------------- RoPE (in place on q and k), q also scaled by DK^-0.5 -----
__global__ void __launch_bounds__(256) rope_kernel(float* __restrict__ q,
                                                   float* __restrict__ k)
{
    size_t idx = (size_t)blockIdx.x * blockDim.x + threadIdx.x;
    const size_t total = (size_t)Bc * Tc * Hc * 64;   // pairs
    if (idx >= total) return;
    int j = (int)(idx & 63);
    size_t rest = idx >> 6;
    int h = (int)(rest & 7);
    size_t bt = rest >> 3;              // b*T + t
    int t = (int)(bt & (Tc - 1));

    float invf = exp2f(-(float)j / 64.f * 13.28771237954945f); // log2(10000)
    float f = (float)t * invf;
    float sv, cv;
    sincosf(f, &sv, &cv);

    size_t base = bt * (Hc * DKc) + (size_t)h * DKc + j;
    const float sc = 0.08838834764831843f; // 128^-0.5

    float q1 = q[base], q2 = q[base + 64];
    q[base]      = (q1 * cv - q2 * sv) * sc;
    q[base + 64] = (q2 * cv + q1 * sv) * sc;

    float k1 = k[base], k2 = k[base + 64];
    k[base]      = k1 * cv - k2 * sv;
    k[base + 64] = k2 * cv + k1 * sv;
}

// ---------------- chunked retention -----------------------------------------
// One block per (b, h, dv-slice of 64). Sequential over 32 chunks.
#define PADR 68
#define SM_QT   0
#define SM_KT   (SM_QT + 128 * PADR)
#define SM_S    (SM_KT + 128 * PADR)
#define SM_VS   (SM_S  + 128 * PADR)
#define SM_ATT  (SM_VS + 64 * PADR)
#define SM_GPOW (SM_ATT + 64 * PADR)
#define SM_FLOATS (SM_GPOW + 65)

__global__ void __launch_bounds__(256) retention_kernel(
    const float* __restrict__ q, const float* __restrict__ k,
    const float* __restrict__ v, float* __restrict__ o)
{
    extern __shared__ float sm[];
    float* qT   = sm + SM_QT;
    float* kT   = sm + SM_KT;
    float* S    = sm + SM_S;
    float* vs   = sm + SM_VS;
    float* attn = sm + SM_ATT;
    float* gpow = sm + SM_GPOW;

    const int bid = blockIdx.x;           // b*32 + h*4 + s
    const int b = bid >> 5;
    const int h = (bid >> 2) & 7;
    const int s = bid & 3;
    const int e0 = s * 64;
    const int tid = threadIdx.x;

    const float gamma = 1.f - exp2f(-5.f - (float)h);
    if (tid < 65) gpow[tid] = powf(gamma, (float)tid);
    for (int idx = tid; idx < 128 * PADR; idx += 256) S[idx] = 0.f;
    __syncthreads();

    const int ti = tid >> 4;   // 0..15
    const int tj = tid & 15;   // 0..15

    for (int n = 0; n < NCHUNK; n++) {
        const size_t rowbase = (size_t)(b * Tc + n * CC);
        for (int idx = tid; idx < 64 * 128; idx += 256) {
            int i = idx >> 7, d = idx & 127;
            size_t gq = (rowbase + i) * (Hc * DKc) + h * DKc + d;
            qT[d * PADR + i] = q[gq];
            kT[d * PADR + i] = k[gq];
        }
        for (int idx = tid; idx < 64 * 64; idx += 256) {
            int i = idx >> 6, e = idx & 63;
            vs[i * PADR + e] = v[(rowbase + i) * (Hc * DVc) + h * DVc + e0 + e];
        }
        __syncthreads();

        // ---- attn = (q k^T) * M ----
        {
            float a4[4][4] = {};
#pragma unroll 4
            for (int d = 0; d < 128; d++) {
                float ar[4], br[4];
                *(float4*)ar = *(float4*)&qT[d * PADR + 4 * ti];
                *(float4*)br = *(float4*)&kT[d * PADR + 4 * tj];
#pragma unroll
                for (int r = 0; r < 4; r++)
#pragma unroll
                    for (int c = 0; c < 4; c++)
                        a4[r][c] = fmaf(ar[r], br[c], a4[r][c]);
            }
#pragma unroll
            for (int r = 0; r < 4; r++) {
                int i = 4 * ti + r;
#pragma unroll
                for (int c = 0; c < 4; c++) {
                    int j = 4 * tj + c;
                    attn[i * PADR + j] = (i >= j) ? a4[r][c] * gpow[i - j] : 0.f;
                }
            }
        }
        __syncthreads();

        // ---- o = attn @ v  +  dec_q * (q @ S_old) ----
        {
            float a4[4][4] = {};
#pragma unroll 4
            for (int d = 0; d < 128; d++) {
                float ar[4], br[4];
                *(float4*)ar = *(float4*)&qT[d * PADR + 4 * ti];
                *(float4*)br = *(float4*)&S[d * PADR + 4 * tj];
#pragma unroll
                for (int r = 0; r < 4; r++)
#pragma unroll
                    for (int c = 0; c < 4; c++)
                        a4[r][c] = fmaf(ar[r], br[c], a4[r][c]);
            }
#pragma unroll
            for (int r = 0; r < 4; r++) {
                float dq = gpow[4 * ti + r + 1];
#pragma unroll
                for (int c = 0; c < 4; c++) a4[r][c] *= dq;
            }
#pragma unroll 4
            for (int j = 0; j < 64; j++) {
                float br[4];
                *(float4*)br = *(float4*)&vs[j * PADR + 4 * tj];
#pragma unroll
                for (int r = 0; r < 4; r++) {
                    float av = attn[(4 * ti + r) * PADR + j];
#pragma unroll
                    for (int c = 0; c < 4; c++)
                        a4[r][c] = fmaf(av, br[c], a4[r][c]);
                }
            }
#pragma unroll
            for (int r = 0; r < 4; r++) {
                size_t orow = (rowbase + 4 * ti + r) * (Hc * DVc) + h * DVc + e0 + 4 * tj;
                *(float4*)&o[orow] = make_float4(a4[r][0], a4[r][1], a4[r][2], a4[r][3]);
            }
        }
        __syncthreads();

        // ---- S = gamma^C * S + (k * dec_k)^T @ v ----
        {
            const int d0 = ti * 8;
            const int eg = tj * 4;
            float acc2[8][4] = {};
#pragma unroll 4
            for (int j = 0; j < 64; j++) {
                float dk = gpow[63 - j];
                float vv[4];
                *(float4*)vv = *(float4*)&vs[j * PADR + eg];
#pragma unroll
                for (int r = 0; r < 8; r++) {
                    float kd = kT[(d0 + r) * PADR + j] * dk;
#pragma unroll
                    for (int c = 0; c < 4; c++)
                        acc2[r][c] = fmaf(kd, vv[c], acc2[r][c]);
                }
            }
            const float gC = gpow[64];
#pragma unroll
            for (int r = 0; r < 8; r++)
#pragma unroll
                for (int c = 0; c < 4; c++) {
                    float* sp = &S[(d0 + r) * PADR + eg + c];
                    *sp = gC * (*sp) + acc2[r][c];
                }
        }
        __syncthreads();
    }
}

// ---------------- RMSNorm over DV + SiLU gate (in place on o) ---------------
__global__ void __launch_bounds__(256) norm_gate_kernel(
    float* __restrict__ o, const float* __restrict__ g,
    const float* __restrict__ norm_w)
{
    const int warp = threadIdx.x >> 5, lane = threadIdx.x & 31;
    const size_t row = (size_t)blockIdx.x * 8 + warp;   // B*T*H rows
    float* orow = o + row * DVc;
    const float* grow = g + row * DVc;

    float vals[8];
    float ss = 0.f;
#pragma unroll
    for (int c = 0; c < 8; c++) {
        float x = orow[lane + 32 * c];
        vals[c] = x;
        ss += x * x;
    }
#pragma unroll
    for (int off = 16; off; off >>= 1) ss += __shfl_xor_sync(0xffffffffu, ss, off);
    const float rinv = rsqrtf(ss * (1.f / DVc) + 1e-5f);

#pragma unroll
    for (int c = 0; c < 8; c++) {
        int e = lane + 32 * c;
        float gv = grow[e];
        float gate = gv / (1.f + expf(-gv));         // g * sigmoid(g)
        orow[e] = vals[c] * rinv * norm_w[e] * gate;
    }
}

// ---------------- launch -----------------------------------------------------
extern "C" void kernel_launch(void* const* d_in, const int* in_sizes, int n_in,
                              void* d_out, int out_size)
{
    const float* x      = (const float*)d_in[0];
    const float* Wq     = (const float*)d_in[1];
    const float* Wk     = (const float*)d_in[2];
    const float* Wv     = (const float*)d_in[3];
    const float* Wg     = (const float*)d_in[4];
    const float* Wo     = (const float*)d_in[5];
    const float* norm_w = (const float*)d_in[6];
    float* out = (float*)d_out;

    float *pq, *pk, *pv, *pg, *po;
    cudaGetSymbolAddress((void**)&pq, g_q);
    cudaGetSymbolAddress((void**)&pk, g_k);
    cudaGetSymbolAddress((void**)&pv, g_v);
    cudaGetSymbolAddress((void**)&pg, g_g);
    cudaGetSymbolAddress((void**)&po, g_o);

    dim3 blk(256);
    // projections (tf32 tensor cores)
    tf32gemm<<<dim3(Hc * DKc / 128, MROWS / 128), blk>>>(x, Wq, pq, MROWS, Hc * DKc, Dc);
    tf32gemm<<<dim3(Hc * DKc / 128, MROWS / 128), blk>>>(x, Wk, pk, MROWS, Hc * DKc, Dc);
    tf32gemm<<<dim3(Hc * DVc / 128, MROWS / 128), blk>>>(x, Wv, pv, MROWS, Hc * DVc, Dc);
    tf32gemm<<<dim3(Hc * DVc / 128, MROWS / 128), blk>>>(x, Wg, pg, MROWS, Hc * DVc, Dc);

    // rope (+ q scale)
    {
        size_t total = (size_t)Bc * Tc * Hc * 64;
        rope_kernel<<<(unsigned)((total + 255) / 256), blk>>>(pq, pk);
    }

    // retention
    {
        const int smem = SM_FLOATS * sizeof(float);
        cudaFuncSetAttribute(retention_kernel,
                             cudaFuncAttributeMaxDynamicSharedMemorySize, smem);
        retention_kernel<<<Bc * Hc * 4, blk, smem>>>(pq, pk, pv, po);
    }

    // rmsnorm + gate
    norm_gate_kernel<<<(Bc * Tc * Hc) / 8, blk>>>(po, pg, norm_w);

    // output projection (tf32 tensor cores)
    tf32gemm<<<dim3(Dc / 128, MROWS / 128), blk>>>(po, Wo, out, MROWS, Dc, Hc * DVc);
}